// round 15
// baseline (speedup 1.0000x reference)
#include <cuda_runtime.h>
#include <cuda_fp16.h>
#include <cstdint>

#define NMAX 50000
#define EMAX 800000
#define NNZMAX (EMAX + NMAX)
#define D 128
#define SCAN_B 512
#define MAXBLK 128   // >= ceil(NMAX/SCAN_B) = 98
#define APITCH 136   // padded row pitch in halves (272B): conflict-free ldmatrix
#define GB 148       // persistent blocks (1/SM)

// ---------------- scratch (device globals: allocation-free) ----------------
__device__ __half g_x16[NMAX * D];
__device__ __half g_h16[NMAX * D];
__device__ __half g_a16[NMAX * D];
__device__ __half g_w16[3 * D * D];
__device__ int    g_cnt[NMAX];
__device__ float  g_dis[NMAX];
__device__ int    g_rowptr[NMAX + 1];
__device__ int    g_cursor[NMAX];
__device__ int    g_col[NNZMAX];
__device__ float  g_val[NNZMAX];
__device__ volatile int g_blk_agg[MAXBLK];
__device__ volatile int g_blk_pfx[MAXBLK];
__device__ volatile int g_blk_flag[MAXBLK];   // 0=invalid 1=agg 2=prefix

// ---------------- mma / async helpers ----------------
__device__ __forceinline__ uint32_t smem_u32(const void* p) {
    return (uint32_t)__cvta_generic_to_shared(p);
}
__device__ __forceinline__ void ldmA(uint32_t* r, uint32_t addr) {
    asm volatile("ldmatrix.sync.aligned.m8n8.x4.shared.b16 {%0,%1,%2,%3}, [%4];"
        : "=r"(r[0]), "=r"(r[1]), "=r"(r[2]), "=r"(r[3]) : "r"(addr));
}
__device__ __forceinline__ void ldmB(uint32_t* r, uint32_t addr) {
    asm volatile("ldmatrix.sync.aligned.m8n8.x2.trans.shared.b16 {%0,%1}, [%2];"
        : "=r"(r[0]), "=r"(r[1]) : "r"(addr));
}
__device__ __forceinline__ void mma16816(float* c, const uint32_t* a, const uint32_t* b) {
    asm volatile("mma.sync.aligned.m16n8k16.row.col.f32.f16.f16.f32 "
        "{%0,%1,%2,%3}, {%4,%5,%6,%7}, {%8,%9}, {%0,%1,%2,%3};"
        : "+f"(c[0]), "+f"(c[1]), "+f"(c[2]), "+f"(c[3])
        : "r"(a[0]), "r"(a[1]), "r"(a[2]), "r"(a[3]), "r"(b[0]), "r"(b[1]));
}
__device__ __forceinline__ void cpa16(uint32_t saddr, const void* gaddr, int ssz) {
    asm volatile("cp.async.cg.shared.global [%0], [%1], 16, %2;"
        :: "r"(saddr), "l"(gaddr), "r"(ssz));
}
__device__ __forceinline__ void cpa_commit() {
    asm volatile("cp.async.commit_group;");
}
template <int N>
__device__ __forceinline__ void cpa_wait() {
    asm volatile("cp.async.wait_group %0;" :: "n"(N));
}

// ---------------- warp-level SpMM row gather (fp32 accum) -------------------
__device__ __forceinline__ float4 gather_row(const __half* __restrict__ h,
                                             int row, int lane) {
    int p0 = g_rowptr[row], p1 = g_rowptr[row + 1];
    float4 acc = make_float4(0.f, 0.f, 0.f, 0.f);
    int p = p0;
    for (; p + 4 <= p1; p += 4) {
        int   c0 = g_col[p],     c1 = g_col[p + 1], c2 = g_col[p + 2], c3 = g_col[p + 3];
        float v0 = g_val[p],     v1 = g_val[p + 1], v2 = g_val[p + 2], v3 = g_val[p + 3];
        uint2 r0 = *(const uint2*)(h + c0 * D + lane * 4);
        uint2 r1 = *(const uint2*)(h + c1 * D + lane * 4);
        uint2 r2 = *(const uint2*)(h + c2 * D + lane * 4);
        uint2 r3 = *(const uint2*)(h + c3 * D + lane * 4);
        float2 a0 = __half22float2(*reinterpret_cast<__half2*>(&r0.x));
        float2 b0 = __half22float2(*reinterpret_cast<__half2*>(&r0.y));
        float2 a1 = __half22float2(*reinterpret_cast<__half2*>(&r1.x));
        float2 b1 = __half22float2(*reinterpret_cast<__half2*>(&r1.y));
        float2 a2 = __half22float2(*reinterpret_cast<__half2*>(&r2.x));
        float2 b2 = __half22float2(*reinterpret_cast<__half2*>(&r2.y));
        float2 a3 = __half22float2(*reinterpret_cast<__half2*>(&r3.x));
        float2 b3 = __half22float2(*reinterpret_cast<__half2*>(&r3.y));
        acc.x = fmaf(v0, a0.x, fmaf(v1, a1.x, fmaf(v2, a2.x, fmaf(v3, a3.x, acc.x))));
        acc.y = fmaf(v0, a0.y, fmaf(v1, a1.y, fmaf(v2, a2.y, fmaf(v3, a3.y, acc.y))));
        acc.z = fmaf(v0, b0.x, fmaf(v1, b1.x, fmaf(v2, b2.x, fmaf(v3, b3.x, acc.z))));
        acc.w = fmaf(v0, b0.y, fmaf(v1, b1.y, fmaf(v2, b2.y, fmaf(v3, b3.y, acc.w))));
    }
    for (; p < p1; ++p) {
        int cI = g_col[p]; float vI = g_val[p];
        uint2 rI = *(const uint2*)(h + cI * D + lane * 4);
        float2 fa = __half22float2(*reinterpret_cast<__half2*>(&rI.x));
        float2 fb = __half22float2(*reinterpret_cast<__half2*>(&rI.y));
        acc.x = fmaf(vI, fa.x, acc.x);
        acc.y = fmaf(vI, fa.y, acc.y);
        acc.z = fmaf(vI, fb.x, acc.z);
        acc.w = fmaf(vI, fb.y, acc.w);
    }
    return acc;
}

// ---------------- CSR build chain (stream B) ----------------
__global__ void k_zero(int n, int nblk) {
    int i = blockIdx.x * blockDim.x + threadIdx.x;
    if (i < n) g_cnt[i] = 0;
    if (i < nblk) {
        g_blk_flag[i] = 0;
        g_blk_agg[i] = 0;
        g_blk_pfx[i] = 0;
    }
}

__global__ void k_count(const int* __restrict__ dst, int e) {
    int i = blockIdx.x * blockDim.x + threadIdx.x;
    if (i < e) atomicAdd(&g_cnt[dst[i]], 1);
}

// single-pass decoupled-lookback scan of (cnt+1); writes dis, rowptr,
// self-loop entry, cursor; last block writes rowptr[n].
__global__ void __launch_bounds__(SCAN_B, 1) k_scan(int n) {
    const int t = threadIdx.x, b = blockIdx.x;
    const int nb = gridDim.x;
    const int i = b * SCAN_B + t;
    const int lane = t & 31, w = t >> 5;

    int v = 0;
    float my_dis = 0.f;
    if (i < n) {
        v = g_cnt[i] + 1;
        my_dis = rsqrtf((float)v);
        g_dis[i] = my_dis;
    }

    // block inclusive scan
    int x = v;
    #pragma unroll
    for (int o = 1; o < 32; o <<= 1) {
        int y = __shfl_up_sync(0xffffffffu, x, o);
        if (lane >= o) x += y;
    }
    __shared__ int wsum[SCAN_B / 32];
    __shared__ int s_total, s_exc;
    if (lane == 31) wsum[w] = x;
    __syncthreads();
    if (t < SCAN_B / 32) {
        int y = wsum[t], z = y;
        #pragma unroll
        for (int o = 1; o < SCAN_B / 32; o <<= 1) {
            int q = __shfl_up_sync(0xffffu, z, o);
            if (t >= o) z += q;
        }
        wsum[t] = z - y;                 // exclusive warp offset
        if (t == SCAN_B / 32 - 1) s_total = z;
    }
    __syncthreads();
    int total = s_total;

    // publish + lookback (thread 0)
    if (t == 0) {
        if (b == 0) {
            g_blk_pfx[0] = total;
            __threadfence();
            g_blk_flag[0] = 2;
            s_exc = 0;
        } else {
            g_blk_agg[b] = total;
            __threadfence();
            g_blk_flag[b] = 1;
            int exc = 0;
            int j = b - 1;
            while (true) {
                int f = g_blk_flag[j];
                if (f == 0) { __nanosleep(32); continue; }
                __threadfence();
                if (f == 2) { exc += g_blk_pfx[j]; break; }
                exc += g_blk_agg[j];
                --j;
            }
            g_blk_pfx[b] = exc + total;
            __threadfence();
            g_blk_flag[b] = 2;
            s_exc = exc;
        }
        if (b == nb - 1) g_rowptr[n] = (b == 0 ? total : s_exc + total);
    }
    __syncthreads();

    int excl = s_exc + wsum[w] + x - v;
    if (i < n) {
        g_rowptr[i] = excl;
        g_col[excl] = i;
        g_val[excl] = my_dis * my_dis;
        g_cursor[i] = excl + 1;
    }
}

__global__ void k_fill_edges(const int* __restrict__ src,
                             const int* __restrict__ dst, int e) {
    int i = blockIdx.x * blockDim.x + threadIdx.x;
    if (i < e) {
        int s = src[i];
        int d_ = dst[i];
        int p = atomicAdd(&g_cursor[d_], 1);
        g_col[p] = s;
        g_val[p] = g_dis[s] * g_dis[d_];
    }
}

// ---------------- convert x, W1..3 to fp16 (main stream) --------------------
__global__ void k_cvt(const float* __restrict__ x,
                      const float* __restrict__ W1,
                      const float* __restrict__ W2,
                      const float* __restrict__ W3, int n4) {
    const int w4 = D * D / 4;  // 4096
    int i = blockIdx.x * blockDim.x + threadIdx.x;
    float4 v;
    uint2* o2;
    int oi;
    if (i < n4) {
        v = ((const float4*)x)[i];
        o2 = (uint2*)g_x16;
        oi = i;
    } else if (i < n4 + 3 * w4) {
        int j = i - n4;
        int w = j / w4, k = j - w * w4;
        const float* W = (w == 0) ? W1 : (w == 1) ? W2 : W3;
        v = ((const float4*)W)[k];
        o2 = (uint2*)(g_w16 + w * D * D);
        oi = k;
    } else return;
    __half2 h0 = __floats2half2_rn(v.x, v.y);
    __half2 h1 = __floats2half2_rn(v.z, v.w);
    uint2 r;
    r.x = *reinterpret_cast<uint32_t*>(&h0);
    r.y = *reinterpret_cast<uint32_t*>(&h1);
    o2[oi] = r;
}

// ---------------- persistent double-buffered HMMA GEMM (512 thr, 16 warps) --
__global__ void __launch_bounds__(512, 1)
k_gemm_mma(const __half* __restrict__ in, const __half* __restrict__ W16,
           __half* __restrict__ out, int nrows, int ntiles) {
    extern __shared__ __half sm16[];
    __half* Ws = sm16;                         // 128 x APITCH
    __half* Ab[2] = { sm16 + 128 * APITCH, sm16 + 2 * 128 * APITCH };
    const int t = threadIdx.x;

    #pragma unroll
    for (int i = t; i < 128 * 16; i += 512) {
        int r = i >> 4, c8 = i & 15;
        *(uint4*)(Ws + r * APITCH + c8 * 8) = ((const uint4*)W16)[r * 16 + c8];
    }

    const int wid = t >> 5, lane = t & 31;
    const int wm = wid & 3, wn = wid >> 2;      // 4 x 4
    const int arow = wm * 32 + (lane & 15);
    const int acol_sel = (lane >> 4) * 8;
    const int brow = lane & 15;
    const int bcol0 = wn * 32;
    const int er = lane >> 2, ec = (lane & 3) * 2;

    int tile = blockIdx.x;
    if (tile >= ntiles) return;

    {
        int row0 = tile * 128;
        #pragma unroll
        for (int j = 0; j < 4; ++j) {
            int i = t + j * 512;
            int r = i >> 4, c8 = i & 15;
            int gr = row0 + r;
            int ok = gr < nrows;
            cpa16(smem_u32(Ab[0] + r * APITCH + c8 * 8),
                  in + (ok ? gr : 0) * D + c8 * 8, ok ? 16 : 0);
        }
        cpa_commit();
    }

    int parity = 0;
    while (tile < ntiles) {
        int next = tile + GB;
        if (next < ntiles) {
            int row0 = next * 128;
            __half* An = Ab[parity ^ 1];
            #pragma unroll
            for (int j = 0; j < 4; ++j) {
                int i = t + j * 512;
                int r = i >> 4, c8 = i & 15;
                int gr = row0 + r;
                int ok = gr < nrows;
                cpa16(smem_u32(An + r * APITCH + c8 * 8),
                      in + (ok ? gr : 0) * D + c8 * 8, ok ? 16 : 0);
            }
            cpa_commit();
            cpa_wait<1>();
        } else {
            cpa_wait<0>();
        }
        __syncthreads();

        const __half* As = Ab[parity];
        float c[2][4][4];
        #pragma unroll
        for (int mi = 0; mi < 2; ++mi)
            #pragma unroll
            for (int ni = 0; ni < 4; ++ni)
                #pragma unroll
                for (int j = 0; j < 4; ++j) c[mi][ni][j] = 0.f;

        #pragma unroll
        for (int k0 = 0; k0 < 128; k0 += 16) {
            uint32_t a[2][4];
            #pragma unroll
            for (int mi = 0; mi < 2; ++mi)
                ldmA(a[mi], smem_u32(As + (arow + mi * 16) * APITCH + k0 + acol_sel));
            uint32_t bf[4][2];
            #pragma unroll
            for (int ni = 0; ni < 4; ++ni)
                ldmB(bf[ni], smem_u32(Ws + (k0 + brow) * APITCH + bcol0 + ni * 8));
            #pragma unroll
            for (int mi = 0; mi < 2; ++mi)
                #pragma unroll
                for (int ni = 0; ni < 4; ++ni)
                    mma16816(c[mi][ni], a[mi], bf[ni]);
        }
        __syncthreads();

        int row0 = tile * 128;
        #pragma unroll
        for (int mi = 0; mi < 2; ++mi) {
            int gr0 = row0 + wm * 32 + mi * 16 + er;
            #pragma unroll
            for (int ni = 0; ni < 4; ++ni) {
                int col = wn * 32 + ni * 8 + ec;
                if (gr0 < nrows) {
                    __half2 v = __floats2half2_rn(c[mi][ni][0], c[mi][ni][1]);
                    *(__half2*)(out + gr0 * D + col) = v;
                }
                if (gr0 + 8 < nrows) {
                    __half2 v = __floats2half2_rn(c[mi][ni][2], c[mi][ni][3]);
                    *(__half2*)(out + (gr0 + 8) * D + col) = v;
                }
            }
        }
        tile = next;
        parity ^= 1;
    }
}

// ---------------- SpMM + bias + relu: one warp/row, fp16 in/out -------------
__global__ void k_spmm(const __half* __restrict__ h, const float* __restrict__ bias,
                       __half* __restrict__ out, int nrows) {
    int w = (blockIdx.x * blockDim.x + threadIdx.x) >> 5;
    int lane = threadIdx.x & 31;
    if (w >= nrows) return;
    float4 acc = gather_row(h, w, lane);
    float4 b = *(const float4*)(bias + lane * 4);
    acc.x = fmaxf(acc.x + b.x, 0.f);
    acc.y = fmaxf(acc.y + b.y, 0.f);
    acc.z = fmaxf(acc.z + b.z, 0.f);
    acc.w = fmaxf(acc.w + b.w, 0.f);
    __half2 o0 = __floats2half2_rn(acc.x, acc.y);
    __half2 o1 = __floats2half2_rn(acc.z, acc.w);
    uint2 ov;
    ov.x = *reinterpret_cast<uint32_t*>(&o0);
    ov.y = *reinterpret_cast<uint32_t*>(&o1);
    *(uint2*)(out + w * D + lane * 4) = ov;
}

// ---------------- pool ----------------
__global__ void k_pool(const __half* __restrict__ a, const int* __restrict__ batch,
                       float* __restrict__ out, int n) {
    int g = blockIdx.x, c = threadIdx.x;
    __shared__ int bounds[2];
    if (c < 2) {
        int target = g + c;
        int lo = 0, hi = n;
        while (lo < hi) {
            int mid = (lo + hi) >> 1;
            if (batch[mid] < target) lo = mid + 1; else hi = mid;
        }
        bounds[c] = lo;
    }
    __syncthreads();
    float sum = 0.f;
    for (int r = bounds[0]; r < bounds[1]; ++r) sum += __half2float(a[r * D + c]);
    out[g * D + c] = sum;
}

// ---------------- launch ----------------
extern "C" void kernel_launch(void* const* d_in, const int* in_sizes, int n_in,
                              void* d_out, int out_size) {
    const float* x  = (const float*)d_in[0];
    const float* W1 = (const float*)d_in[1];
    const float* b1 = (const float*)d_in[2];
    const float* W2 = (const float*)d_in[3];
    const float* b2 = (const float*)d_in[4];
    const float* W3 = (const float*)d_in[5];
    const float* b3 = (const float*)d_in[6];
    const int* ei    = (const int*)d_in[7];
    const int* batch = (const int*)d_in[8];
    float* out = (float*)d_out;

    int N = in_sizes[0] / D;
    int E = in_sizes[7] / 2;
    int G = out_size / D;

    __half *xbuf, *hbuf, *abuf, *wbuf;
    cudaGetSymbolAddress((void**)&xbuf, g_x16);
    cudaGetSymbolAddress((void**)&hbuf, g_h16);
    cudaGetSymbolAddress((void**)&abuf, g_a16);
    cudaGetSymbolAddress((void**)&wbuf, g_w16);

    int smem3 = 3 * 128 * APITCH * (int)sizeof(__half);  // 104448 B
    cudaFuncSetAttribute(k_gemm_mma, cudaFuncAttributeMaxDynamicSharedMemorySize, smem3);

    static cudaStream_t s2 = nullptr;
    static cudaEvent_t evFork = nullptr, evJoin = nullptr;
    if (s2 == nullptr) {
        cudaStreamCreateWithFlags(&s2, cudaStreamNonBlocking);
        cudaEventCreateWithFlags(&evFork, cudaEventDisableTiming);
        cudaEventCreateWithFlags(&evJoin, cudaEventDisableTiming);
    }

    int nb = (N + 255) / 256;
    int eb = (E + 255) / 256;
    int sbk = (N + SCAN_B - 1) / SCAN_B;   // 98
    int n4 = N * D / 4;
    int cvt_total = n4 + 3 * (D * D / 4);
    int ntiles = (N + 127) / 128;
    int gb = ntiles < GB ? ntiles : GB;
    int sb = (N * 32 + 511) / 512;

    // fork: CSR chain on s2, concurrent with cvt+gemm1 on main stream
    cudaEventRecord(evFork, 0);
    cudaStreamWaitEvent(s2, evFork, 0);
    k_zero<<<nb, 256, 0, s2>>>(N, sbk);
    k_count<<<eb, 256, 0, s2>>>(ei + E, E);
    k_scan<<<sbk, SCAN_B, 0, s2>>>(N);
    k_fill_edges<<<eb, 256, 0, s2>>>(ei, ei + E, E);
    cudaEventRecord(evJoin, s2);

    k_cvt<<<(cvt_total + 255) / 256, 256>>>(x, W1, W2, W3, n4);
    k_gemm_mma<<<gb, 512, smem3>>>(xbuf, wbuf, hbuf, N, ntiles);

    cudaStreamWaitEvent(0, evJoin, 0);

    k_spmm<<<sb, 512>>>(hbuf, b1, abuf, N);
    k_gemm_mma<<<gb, 512, smem3>>>(abuf, wbuf + D * D, hbuf, N, ntiles);
    k_spmm<<<sb, 512>>>(hbuf, b2, abuf, N);
    k_gemm_mma<<<gb, 512, smem3>>>(abuf, wbuf + 2 * D * D, hbuf, N, ntiles);
    k_spmm<<<sb, 512>>>(hbuf, b3, abuf, N);

    k_pool<<<G, 128>>>(abuf, batch, out, N);
}

// round 17
// speedup vs baseline: 1.0777x; 1.0777x over previous
#include <cuda_runtime.h>
#include <cuda_fp16.h>
#include <cstdint>

#define NMAX 50000
#define EMAX 800000
#define NNZMAX (EMAX + NMAX)
#define D 128
#define SCAN_B 512
#define APITCH 136   // padded row pitch in halves (272B): conflict-free ldmatrix
#define GB 148       // persistent blocks (1/SM)

// ---------------- scratch (device globals: allocation-free) ----------------
__device__ __half g_x16[NMAX * D];
__device__ __half g_h16[NMAX * D];
__device__ __half g_a16[NMAX * D];
__device__ __half g_w16[3 * D * D];
__device__ int    g_cnt[NMAX];
__device__ float  g_dis[NMAX];
__device__ int    g_rowptr[NMAX + 1];
__device__ int    g_cursor[NMAX];
__device__ int2   g_cv[NNZMAX];       // packed {col, val-bits}: 1x8B scattered write
__device__ int    g_bsum[128];
__device__ int    g_boff[128];

// ---------------- mma / async helpers ----------------
__device__ __forceinline__ uint32_t smem_u32(const void* p) {
    return (uint32_t)__cvta_generic_to_shared(p);
}
__device__ __forceinline__ void ldmA(uint32_t* r, uint32_t addr) {
    asm volatile("ldmatrix.sync.aligned.m8n8.x4.shared.b16 {%0,%1,%2,%3}, [%4];"
        : "=r"(r[0]), "=r"(r[1]), "=r"(r[2]), "=r"(r[3]) : "r"(addr));
}
__device__ __forceinline__ void ldmB(uint32_t* r, uint32_t addr) {
    asm volatile("ldmatrix.sync.aligned.m8n8.x2.trans.shared.b16 {%0,%1}, [%2];"
        : "=r"(r[0]), "=r"(r[1]) : "r"(addr));
}
__device__ __forceinline__ void mma16816(float* c, const uint32_t* a, const uint32_t* b) {
    asm volatile("mma.sync.aligned.m16n8k16.row.col.f32.f16.f16.f32 "
        "{%0,%1,%2,%3}, {%4,%5,%6,%7}, {%8,%9}, {%0,%1,%2,%3};"
        : "+f"(c[0]), "+f"(c[1]), "+f"(c[2]), "+f"(c[3])
        : "r"(a[0]), "r"(a[1]), "r"(a[2]), "r"(a[3]), "r"(b[0]), "r"(b[1]));
}
__device__ __forceinline__ void cpa16(uint32_t saddr, const void* gaddr, int ssz) {
    asm volatile("cp.async.cg.shared.global [%0], [%1], 16, %2;"
        :: "r"(saddr), "l"(gaddr), "r"(ssz));
}
__device__ __forceinline__ void cpa_commit() {
    asm volatile("cp.async.commit_group;");
}
template <int N>
__device__ __forceinline__ void cpa_wait() {
    asm volatile("cp.async.wait_group %0;" :: "n"(N));
}

// ---------------- warp-level SpMM row gather (fp32 accum) -------------------
__device__ __forceinline__ float4 gather_row(const __half* __restrict__ h,
                                             int row, int lane) {
    int p0 = g_rowptr[row], p1 = g_rowptr[row + 1];
    float4 acc = make_float4(0.f, 0.f, 0.f, 0.f);
    int p = p0;
    for (; p + 4 <= p1; p += 4) {
        int2 cv0 = g_cv[p];
        int2 cv1 = g_cv[p + 1];
        int2 cv2 = g_cv[p + 2];
        int2 cv3 = g_cv[p + 3];
        int   c0 = cv0.x, c1 = cv1.x, c2 = cv2.x, c3 = cv3.x;
        float v0 = __int_as_float(cv0.y), v1 = __int_as_float(cv1.y);
        float v2 = __int_as_float(cv2.y), v3 = __int_as_float(cv3.y);
        uint2 r0 = *(const uint2*)(h + c0 * D + lane * 4);
        uint2 r1 = *(const uint2*)(h + c1 * D + lane * 4);
        uint2 r2 = *(const uint2*)(h + c2 * D + lane * 4);
        uint2 r3 = *(const uint2*)(h + c3 * D + lane * 4);
        float2 a0 = __half22float2(*reinterpret_cast<__half2*>(&r0.x));
        float2 b0 = __half22float2(*reinterpret_cast<__half2*>(&r0.y));
        float2 a1 = __half22float2(*reinterpret_cast<__half2*>(&r1.x));
        float2 b1 = __half22float2(*reinterpret_cast<__half2*>(&r1.y));
        float2 a2 = __half22float2(*reinterpret_cast<__half2*>(&r2.x));
        float2 b2 = __half22float2(*reinterpret_cast<__half2*>(&r2.y));
        float2 a3 = __half22float2(*reinterpret_cast<__half2*>(&r3.x));
        float2 b3 = __half22float2(*reinterpret_cast<__half2*>(&r3.y));
        acc.x = fmaf(v0, a0.x, fmaf(v1, a1.x, fmaf(v2, a2.x, fmaf(v3, a3.x, acc.x))));
        acc.y = fmaf(v0, a0.y, fmaf(v1, a1.y, fmaf(v2, a2.y, fmaf(v3, a3.y, acc.y))));
        acc.z = fmaf(v0, b0.x, fmaf(v1, b1.x, fmaf(v2, b2.x, fmaf(v3, b3.x, acc.z))));
        acc.w = fmaf(v0, b0.y, fmaf(v1, b1.y, fmaf(v2, b2.y, fmaf(v3, b3.y, acc.w))));
    }
    for (; p < p1; ++p) {
        int2 cv = g_cv[p];
        int cI = cv.x;
        float vI = __int_as_float(cv.y);
        uint2 rI = *(const uint2*)(h + cI * D + lane * 4);
        float2 fa = __half22float2(*reinterpret_cast<__half2*>(&rI.x));
        float2 fb = __half22float2(*reinterpret_cast<__half2*>(&rI.y));
        acc.x = fmaf(vI, fa.x, acc.x);
        acc.y = fmaf(vI, fa.y, acc.y);
        acc.z = fmaf(vI, fb.x, acc.z);
        acc.w = fmaf(vI, fb.y, acc.w);
    }
    return acc;
}

// ---------------- CSR build chain (stream B) ----------------
__global__ void k_zero(int n) {
    int i = blockIdx.x * blockDim.x + threadIdx.x;
    if (i < n) g_cnt[i] = 0;
}

__global__ void k_count(const int* __restrict__ dst, int e) {
    int i = blockIdx.x * blockDim.x + threadIdx.x;
    if (i < e) atomicAdd(&g_cnt[dst[i]], 1);
}

__global__ void k_scanA(int n) {
    int t = threadIdx.x;
    int i = blockIdx.x * SCAN_B + t;
    int c = (i < n) ? g_cnt[i] : -1;
    int v = c + 1;
    if (i < n) g_dis[i] = rsqrtf((float)v);
    int s = v;
    #pragma unroll
    for (int o = 16; o; o >>= 1) s += __shfl_down_sync(0xffffffffu, s, o);
    __shared__ int ws[SCAN_B / 32];
    if ((t & 31) == 0) ws[t >> 5] = s;
    __syncthreads();
    if (t < SCAN_B / 32) {
        int x = ws[t];
        #pragma unroll
        for (int o = SCAN_B / 64; o; o >>= 1) x += __shfl_down_sync(0xffffu, x, o);
        if (t == 0) g_bsum[blockIdx.x] = x;
    }
}

__global__ void k_scanC(int n) {
    int t = threadIdx.x, b = blockIdx.x;
    int i = b * SCAN_B + t;
    int v = (i < n) ? g_cnt[i] + 1 : 0;
    int lane = t & 31, w = t >> 5;

    __shared__ int s_boff, s_total;
    {
        int nb = gridDim.x;
        int part = 0, full = 0;
        for (int j = t; j < nb; j += SCAN_B) {
            int bs = g_bsum[j];
            full += bs;
            if (j < b) part += bs;
        }
        #pragma unroll
        for (int o = 16; o; o >>= 1) {
            part += __shfl_down_sync(0xffffffffu, part, o);
            full += __shfl_down_sync(0xffffffffu, full, o);
        }
        __shared__ int wp[SCAN_B / 32], wf[SCAN_B / 32];
        if (lane == 0) { wp[w] = part; wf[w] = full; }
        __syncthreads();
        if (t == 0) {
            int sp = 0, sf = 0;
            #pragma unroll
            for (int j = 0; j < SCAN_B / 32; ++j) { sp += wp[j]; sf += wf[j]; }
            s_boff = sp;
            s_total = sf;
        }
    }

    int x = v;
    #pragma unroll
    for (int o = 1; o < 32; o <<= 1) {
        int y = __shfl_up_sync(0xffffffffu, x, o);
        if (lane >= o) x += y;
    }
    __shared__ int wsum[SCAN_B / 32];
    if (lane == 31) wsum[w] = x;
    __syncthreads();
    if (t < SCAN_B / 32) {
        int y = wsum[t], z = y;
        #pragma unroll
        for (int o = 1; o < SCAN_B / 32; o <<= 1) {
            int q = __shfl_up_sync(0xffffu, z, o);
            if (t >= o) z += q;
        }
        wsum[t] = z - y;
    }
    __syncthreads();
    int excl = s_boff + wsum[w] + x - v;
    if (i < n) {
        g_rowptr[i] = excl;
        float d_ = g_dis[i];
        int2 cv;
        cv.x = i;
        cv.y = __float_as_int(d_ * d_);
        g_cv[excl] = cv;
        g_cursor[i] = excl + 1;
    }
    if (b == gridDim.x - 1 && t == 0) g_rowptr[n] = s_total;
}

__global__ void k_fill_edges(const int* __restrict__ src,
                             const int* __restrict__ dst, int e) {
    int i = blockIdx.x * blockDim.x + threadIdx.x;
    if (i < e) {
        int s = src[i];
        int d_ = dst[i];
        int p = atomicAdd(&g_cursor[d_], 1);
        int2 cv;
        cv.x = s;
        cv.y = __float_as_int(g_dis[s] * g_dis[d_]);
        g_cv[p] = cv;   // one 8B scattered write (was two 4B to separate arrays)
    }
}

// ---------------- convert x, W1..3 to fp16 (main stream) --------------------
__global__ void k_cvt(const float* __restrict__ x,
                      const float* __restrict__ W1,
                      const float* __restrict__ W2,
                      const float* __restrict__ W3, int n4) {
    const int w4 = D * D / 4;  // 4096
    int i = blockIdx.x * blockDim.x + threadIdx.x;
    float4 v;
    uint2* o2;
    int oi;
    if (i < n4) {
        v = ((const float4*)x)[i];
        o2 = (uint2*)g_x16;
        oi = i;
    } else if (i < n4 + 3 * w4) {
        int j = i - n4;
        int w = j / w4, k = j - w * w4;
        const float* W = (w == 0) ? W1 : (w == 1) ? W2 : W3;
        v = ((const float4*)W)[k];
        o2 = (uint2*)(g_w16 + w * D * D);
        oi = k;
    } else return;
    __half2 h0 = __floats2half2_rn(v.x, v.y);
    __half2 h1 = __floats2half2_rn(v.z, v.w);
    uint2 r;
    r.x = *reinterpret_cast<uint32_t*>(&h0);
    r.y = *reinterpret_cast<uint32_t*>(&h1);
    o2[oi] = r;
}

// ---------------- persistent double-buffered HMMA GEMM (512 thr, 16 warps) --
__global__ void __launch_bounds__(512, 1)
k_gemm_mma(const __half* __restrict__ in, const __half* __restrict__ W16,
           __half* __restrict__ out, int nrows, int ntiles) {
    extern __shared__ __half sm16[];
    __half* Ws = sm16;                         // 128 x APITCH
    __half* Ab[2] = { sm16 + 128 * APITCH, sm16 + 2 * 128 * APITCH };
    const int t = threadIdx.x;

    #pragma unroll
    for (int i = t; i < 128 * 16; i += 512) {
        int r = i >> 4, c8 = i & 15;
        *(uint4*)(Ws + r * APITCH + c8 * 8) = ((const uint4*)W16)[r * 16 + c8];
    }

    const int wid = t >> 5, lane = t & 31;
    const int wm = wid & 3, wn = wid >> 2;      // 4 x 4
    const int arow = wm * 32 + (lane & 15);
    const int acol_sel = (lane >> 4) * 8;
    const int brow = lane & 15;
    const int bcol0 = wn * 32;
    const int er = lane >> 2, ec = (lane & 3) * 2;

    int tile = blockIdx.x;
    if (tile >= ntiles) return;

    {
        int row0 = tile * 128;
        #pragma unroll
        for (int j = 0; j < 4; ++j) {
            int i = t + j * 512;
            int r = i >> 4, c8 = i & 15;
            int gr = row0 + r;
            int ok = gr < nrows;
            cpa16(smem_u32(Ab[0] + r * APITCH + c8 * 8),
                  in + (ok ? gr : 0) * D + c8 * 8, ok ? 16 : 0);
        }
        cpa_commit();
    }

    int parity = 0;
    while (tile < ntiles) {
        int next = tile + GB;
        if (next < ntiles) {
            int row0 = next * 128;
            __half* An = Ab[parity ^ 1];
            #pragma unroll
            for (int j = 0; j < 4; ++j) {
                int i = t + j * 512;
                int r = i >> 4, c8 = i & 15;
                int gr = row0 + r;
                int ok = gr < nrows;
                cpa16(smem_u32(An + r * APITCH + c8 * 8),
                      in + (ok ? gr : 0) * D + c8 * 8, ok ? 16 : 0);
            }
            cpa_commit();
            cpa_wait<1>();
        } else {
            cpa_wait<0>();
        }
        __syncthreads();

        const __half* As = Ab[parity];
        float c[2][4][4];
        #pragma unroll
        for (int mi = 0; mi < 2; ++mi)
            #pragma unroll
            for (int ni = 0; ni < 4; ++ni)
                #pragma unroll
                for (int j = 0; j < 4; ++j) c[mi][ni][j] = 0.f;

        #pragma unroll
        for (int k0 = 0; k0 < 128; k0 += 16) {
            uint32_t a[2][4];
            #pragma unroll
            for (int mi = 0; mi < 2; ++mi)
                ldmA(a[mi], smem_u32(As + (arow + mi * 16) * APITCH + k0 + acol_sel));
            uint32_t bf[4][2];
            #pragma unroll
            for (int ni = 0; ni < 4; ++ni)
                ldmB(bf[ni], smem_u32(Ws + (k0 + brow) * APITCH + bcol0 + ni * 8));
            #pragma unroll
            for (int mi = 0; mi < 2; ++mi)
                #pragma unroll
                for (int ni = 0; ni < 4; ++ni)
                    mma16816(c[mi][ni], a[mi], bf[ni]);
        }
        __syncthreads();

        int row0 = tile * 128;
        #pragma unroll
        for (int mi = 0; mi < 2; ++mi) {
            int gr0 = row0 + wm * 32 + mi * 16 + er;
            #pragma unroll
            for (int ni = 0; ni < 4; ++ni) {
                int col = wn * 32 + ni * 8 + ec;
                if (gr0 < nrows) {
                    __half2 v = __floats2half2_rn(c[mi][ni][0], c[mi][ni][1]);
                    *(__half2*)(out + gr0 * D + col) = v;
                }
                if (gr0 + 8 < nrows) {
                    __half2 v = __floats2half2_rn(c[mi][ni][2], c[mi][ni][3]);
                    *(__half2*)(out + (gr0 + 8) * D + col) = v;
                }
            }
        }
        tile = next;
        parity ^= 1;
    }
}

// ---------------- SpMM + bias + relu: one warp/row, fp16 in/out -------------
__global__ void k_spmm(const __half* __restrict__ h, const float* __restrict__ bias,
                       __half* __restrict__ out, int nrows) {
    int w = (blockIdx.x * blockDim.x + threadIdx.x) >> 5;
    int lane = threadIdx.x & 31;
    if (w >= nrows) return;
    float4 acc = gather_row(h, w, lane);
    float4 b = *(const float4*)(bias + lane * 4);
    acc.x = fmaxf(acc.x + b.x, 0.f);
    acc.y = fmaxf(acc.y + b.y, 0.f);
    acc.z = fmaxf(acc.z + b.z, 0.f);
    acc.w = fmaxf(acc.w + b.w, 0.f);
    __half2 o0 = __floats2half2_rn(acc.x, acc.y);
    __half2 o1 = __floats2half2_rn(acc.z, acc.w);
    uint2 ov;
    ov.x = *reinterpret_cast<uint32_t*>(&o0);
    ov.y = *reinterpret_cast<uint32_t*>(&o1);
    *(uint2*)(out + w * D + lane * 4) = ov;
}

// ---------------- pool ----------------
__global__ void k_pool(const __half* __restrict__ a, const int* __restrict__ batch,
                       float* __restrict__ out, int n) {
    int g = blockIdx.x, c = threadIdx.x;
    __shared__ int bounds[2];
    if (c < 2) {
        int target = g + c;
        int lo = 0, hi = n;
        while (lo < hi) {
            int mid = (lo + hi) >> 1;
            if (batch[mid] < target) lo = mid + 1; else hi = mid;
        }
        bounds[c] = lo;
    }
    __syncthreads();
    float sum = 0.f;
    for (int r = bounds[0]; r < bounds[1]; ++r) sum += __half2float(a[r * D + c]);
    out[g * D + c] = sum;
}

// ---------------- launch ----------------
extern "C" void kernel_launch(void* const* d_in, const int* in_sizes, int n_in,
                              void* d_out, int out_size) {
    const float* x  = (const float*)d_in[0];
    const float* W1 = (const float*)d_in[1];
    const float* b1 = (const float*)d_in[2];
    const float* W2 = (const float*)d_in[3];
    const float* b2 = (const float*)d_in[4];
    const float* W3 = (const float*)d_in[5];
    const float* b3 = (const float*)d_in[6];
    const int* ei    = (const int*)d_in[7];
    const int* batch = (const int*)d_in[8];
    float* out = (float*)d_out;

    int N = in_sizes[0] / D;
    int E = in_sizes[7] / 2;
    int G = out_size / D;

    __half *xbuf, *hbuf, *abuf, *wbuf;
    cudaGetSymbolAddress((void**)&xbuf, g_x16);
    cudaGetSymbolAddress((void**)&hbuf, g_h16);
    cudaGetSymbolAddress((void**)&abuf, g_a16);
    cudaGetSymbolAddress((void**)&wbuf, g_w16);

    int smem3 = 3 * 128 * APITCH * (int)sizeof(__half);  // 104448 B
    cudaFuncSetAttribute(k_gemm_mma, cudaFuncAttributeMaxDynamicSharedMemorySize, smem3);

    static cudaStream_t s2 = nullptr;
    static cudaEvent_t evFork = nullptr, evJoin = nullptr;
    if (s2 == nullptr) {
        cudaStreamCreateWithFlags(&s2, cudaStreamNonBlocking);
        cudaEventCreateWithFlags(&evFork, cudaEventDisableTiming);
        cudaEventCreateWithFlags(&evJoin, cudaEventDisableTiming);
    }

    int nb = (N + 255) / 256;
    int eb = (E + 255) / 256;
    int sbk = (N + SCAN_B - 1) / SCAN_B;
    int n4 = N * D / 4;
    int cvt_total = n4 + 3 * (D * D / 4);
    int ntiles = (N + 127) / 128;
    int gb = ntiles < GB ? ntiles : GB;
    int sb = (N * 32 + 511) / 512;

    // fork: CSR chain on s2, concurrent with cvt+gemm1 on main stream
    cudaEventRecord(evFork, 0);
    cudaStreamWaitEvent(s2, evFork, 0);
    k_zero<<<nb, 256, 0, s2>>>(N);
    k_count<<<eb, 256, 0, s2>>>(ei + E, E);
    k_scanA<<<sbk, SCAN_B, 0, s2>>>(N);
    k_scanC<<<sbk, SCAN_B, 0, s2>>>(N);
    k_fill_edges<<<eb, 256, 0, s2>>>(ei, ei + E, E);
    cudaEventRecord(evJoin, s2);

    k_cvt<<<(cvt_total + 255) / 256, 256>>>(x, W1, W2, W3, n4);
    k_gemm_mma<<<gb, 512, smem3>>>(xbuf, wbuf, hbuf, N, ntiles);

    cudaStreamWaitEvent(0, evJoin, 0);

    k_spmm<<<sb, 512>>>(hbuf, b1, abuf, N);
    k_gemm_mma<<<gb, 512, smem3>>>(abuf, wbuf + D * D, hbuf, N, ntiles);
    k_spmm<<<sb, 512>>>(hbuf, b2, abuf, N);
    k_gemm_mma<<<gb, 512, smem3>>>(abuf, wbuf + 2 * D * D, hbuf, N, ntiles);
    k_spmm<<<sb, 512>>>(hbuf, b3, abuf, N);

    k_pool<<<G, 128>>>(abuf, batch, out, N);
}